// round 14
// baseline (speedup 1.0000x reference)
#include <cuda_runtime.h>
#include <mma.h>
#include <math.h>
#include <stdint.h>

using namespace nvcuda;

#define TOTPTS 16384
#define MROWS  131072   // TOT*NV
#define KDIM   2048
#define NDIM   512

// Static device scratch (no runtime allocation allowed).
__device__ float g_W0T[(size_t)NDIM * KDIM];       // W0^T [n][k], tf32-RN, 4MB
__device__ float g_part[(size_t)4 * MROWS * 32];   // per-N-chunk partial B32, 64MB

__device__ __forceinline__ float eluf(float x) { return x > 0.f ? x : expm1f(x); }
__device__ __forceinline__ float sigm(float x) { return 1.f / (1.f + expf(-x)); }
__device__ __forceinline__ float wrsum(float v) {
#pragma unroll
    for (int o = 16; o > 0; o >>= 1) v += __shfl_xor_sync(0xffffffffu, v, o);
    return v;
}
__device__ __forceinline__ float rnd_tf32(float x) {
    float r;
    asm("cvt.rna.tf32.f32 %0, %1;" : "=f"(r) : "f"(x));
    return r;
}
__device__ __forceinline__ uint32_t smem_u32(const void* p) {
    uint32_t a;
    asm("{ .reg .u64 t; cvta.to.shared.u64 t, %1; cvt.u32.u64 %0, t; }" : "=r"(a) : "l"(p));
    return a;
}
__device__ __forceinline__ void bulkcp(uint32_t dst, const void* src, uint32_t bytes,
                                       uint32_t bar) {
    asm volatile("cp.async.bulk.shared::cta.global.mbarrier::complete_tx::bytes "
                 "[%0], [%1], %2, [%3];"
                 :: "r"(dst), "l"(src), "r"(bytes), "r"(bar) : "memory");
}
__device__ __forceinline__ void ldsm4(uint32_t& r0, uint32_t& r1, uint32_t& r2, uint32_t& r3,
                                      uint32_t addr) {
    asm volatile("ldmatrix.sync.aligned.m8n8.x4.shared.b16 {%0,%1,%2,%3}, [%4];"
                 : "=r"(r0), "=r"(r1), "=r"(r2), "=r"(r3) : "r"(addr));
}
__device__ __forceinline__ void mma8(float* d, const uint32_t* a, const uint32_t* b) {
    asm volatile("mma.sync.aligned.m16n8k8.row.col.f32.tf32.tf32.f32 "
                 "{%0,%1,%2,%3}, {%4,%5,%6,%7}, {%8,%9}, {%0,%1,%2,%3};"
                 : "+f"(d[0]), "+f"(d[1]), "+f"(d[2]), "+f"(d[3])
                 : "r"(a[0]), "r"(a[1]), "r"(a[2]), "r"(a[3]), "r"(b[0]), "r"(b[1]));
}
#define MBAR_INIT(a, c) asm volatile("mbarrier.init.shared.b64 [%0], %1;" :: "r"(a), "r"(c) : "memory")
#define MBAR_EXPECT(a, tx) asm volatile("mbarrier.arrive.expect_tx.shared.b64 _, [%0], %1;" :: "r"(a), "r"(tx) : "memory")
#define MBAR_WAIT(a, ph) do {                                                              \
    uint32_t _m = (a), _p = (ph), _d;                                                      \
    asm volatile("{\n\t.reg .pred p;\n\t"                                                  \
                 "mbarrier.try_wait.parity.acquire.cta.shared::cta.b64 p, [%1], %2;\n\t"   \
                 "selp.b32 %0, 1, 0, p;\n\t}" : "=r"(_d) : "r"(_m), "r"(_p) : "memory");   \
    if (!_d) {                                                                             \
        asm volatile("{\n\t.reg .pred P1;\n\t"                                             \
            "WL%=:\n\t"                                                                    \
            "mbarrier.try_wait.parity.acquire.cta.shared::cta.b64 P1, [%0], %1, 0x989680;\n\t" \
            "@P1 bra.uni WD%=;\n\t"                                                        \
            "bra.uni WL%=;\n\t"                                                            \
            "WD%=:\n\t}" :: "r"(_m), "r"(_p) : "memory");                                  \
    }                                                                                      \
} while (0)
#define FENCE_PROXY() asm volatile("fence.proxy.async.shared::cta;" ::: "memory")

// ---------------------------------------------------------------------------
// PREP: g_W0T[n][k] = rn_tf32(W0[k][n])
// ---------------------------------------------------------------------------
__global__ void prep_w0t(const float* __restrict__ W0) {
    __shared__ float tile[32][33];
    int n0 = blockIdx.x * 32, k0 = blockIdx.y * 32;
    int tx = threadIdx.x, ty = threadIdx.y;
#pragma unroll
    for (int j = 0; j < 32; j += 8)
        tile[ty + j][tx] = W0[(size_t)(k0 + ty + j) * NDIM + n0 + tx];
    __syncthreads();
#pragma unroll
    for (int j = 0; j < 32; j += 8)
        g_W0T[(size_t)(n0 + ty + j) * KDIM + k0 + tx] = rnd_tf32(tile[tx][ty + j]);
}

// ---------------------------------------------------------------------------
// GEMM1 (at legacy tensor-pipe ceiling — verified rt16 model; unchanged).
// ---------------------------------------------------------------------------
#define STAGEB   36864
#define SMEM_G1  88064
#define HS_F     256
#define W1S_F    17152

__global__ void __launch_bounds__(256, 2) gemm1_kernel(
    const float* __restrict__ X, const float* __restrict__ b0,
    const float* __restrict__ W1)
{
    extern __shared__ float sm[];
    const uint32_t smem = smem_u32(sm);
    const int tid = threadIdx.x, wid = tid >> 5, lane = tid & 31;
    const int p = blockIdx.x, m0 = blockIdx.y * 128, n0 = p * 128;
    const int wm = (wid >> 2) * 64, wn = (wid & 3) * 32;

    if (tid < 128) sm[32 + tid] = b0[n0 + tid];
    if (tid == 0) {
        MBAR_INIT(smem + 16, 1);
        MBAR_INIT(smem + 24, 1);
        FENCE_PROXY();
    }
    __syncthreads();

    const bool isA = tid < 128;
    const int row = tid & 127;
    const float* srcbase = isA ? (X + (size_t)(m0 + row) * KDIM)
                               : (g_W0T + (size_t)(n0 + row) * KDIM);
    const uint32_t dsto = (isA ? 0u : 18432u) + (uint32_t)row * 144u;

    float acc[4][4][4];
#pragma unroll
    for (int g = 0; g < 4; g++)
#pragma unroll
        for (int j = 0; j < 4; j++)
#pragma unroll
            for (int e = 0; e < 4; e++) acc[g][j][e] = 0.f;

    const int rA = lane & 15, hA = (lane >> 4) & 1;
    const int rB = (lane & 7) + ((lane >> 4) & 1) * 8, hB = (lane >> 3) & 1;
    const uint32_t aoff = (uint32_t)(wm + rA) * 144u + (uint32_t)hA * 16u;
    const uint32_t boff = 18432u + (uint32_t)(wn + rB) * 144u + (uint32_t)hB * 16u;

#pragma unroll
    for (int t = 0; t < 2; t++) {
        uint32_t bar = smem + 16 + 8 * t;
        if (tid == 0) MBAR_EXPECT(bar, 32768);
        __syncwarp();
        bulkcp(smem + 1024 + t * STAGEB + dsto, srcbase + t * 32, 128, bar);
    }

    for (int t = 0; t < 64; t++) {
        const int s = t & 1;
        MBAR_WAIT(smem + 16 + 8 * s, (t >> 1) & 1);

        const uint32_t base = smem + 1024 + s * STAGEB;
#pragma unroll
        for (int ks = 0; ks < 4; ks++) {
            uint32_t a[4][4], b[2][4];
#pragma unroll
            for (int g = 0; g < 4; g++)
                ldsm4(a[g][0], a[g][1], a[g][2], a[g][3],
                      base + aoff + (uint32_t)g * 2304u + (uint32_t)ks * 32u);
#pragma unroll
            for (int jj = 0; jj < 2; jj++)
                ldsm4(b[jj][0], b[jj][1], b[jj][2], b[jj][3],
                      base + boff + (uint32_t)jj * 2304u + (uint32_t)ks * 32u);
#pragma unroll
            for (int g = 0; g < 4; g++)
#pragma unroll
                for (int e = 0; e < 4; e++)
                    a[g][e] = __float_as_uint(rnd_tf32(__uint_as_float(a[g][e])));
#pragma unroll
            for (int g = 0; g < 4; g++) {
                mma8(acc[g][0], a[g], &b[0][0]);
                mma8(acc[g][1], a[g], &b[0][2]);
                mma8(acc[g][2], a[g], &b[1][0]);
                mma8(acc[g][3], a[g], &b[1][2]);
            }
        }
        __syncthreads();
        if (t + 2 < 64) {
            uint32_t bar = smem + 16 + 8 * s;
            if (tid == 0) MBAR_EXPECT(bar, 32768);
            bulkcp(smem + 1024 + s * STAGEB + dsto, srcbase + (t + 2) * 32, 128, bar);
        }
    }

    float* Hs  = sm + HS_F;
    float* W1s = sm + W1S_F;
    {
        const int tr = lane >> 2, tc = 2 * (lane & 3);
#pragma unroll
        for (int g = 0; g < 4; g++)
#pragma unroll
            for (int j = 0; j < 4; j++) {
                int R0 = wm + g * 16 + tr, C = wn + j * 8 + tc;
                float b0c0 = sm[32 + C], b0c1 = sm[32 + C + 1];
                float2 v0, v1;
                v0.x = rnd_tf32(eluf(acc[g][j][0] + b0c0));
                v0.y = rnd_tf32(eluf(acc[g][j][1] + b0c1));
                v1.x = rnd_tf32(eluf(acc[g][j][2] + b0c0));
                v1.y = rnd_tf32(eluf(acc[g][j][3] + b0c1));
                *(float2*)&Hs[R0 * 132 + C] = v0;
                *(float2*)&Hs[(R0 + 8) * 132 + C] = v1;
            }
    }
    for (int i = tid; i < 128 * 32; i += 256) {
        int r = i >> 5, c = i & 31;
        W1s[r * 36 + c] = rnd_tf32(W1[(size_t)(n0 + r) * 32 + c]);
    }
    __syncthreads();

    {
        int r0 = wid * 16;
        wmma::fragment<wmma::accumulator, 16, 16, 8, float> oacc[2];
        wmma::fill_fragment(oacc[0], 0.f);
        wmma::fill_fragment(oacc[1], 0.f);
#pragma unroll
        for (int kk = 0; kk < 16; kk++) {
            wmma::fragment<wmma::matrix_a, 16, 16, 8, wmma::precision::tf32, wmma::row_major> af;
            wmma::fragment<wmma::matrix_b, 16, 16, 8, wmma::precision::tf32, wmma::row_major> bf0, bf1;
            wmma::load_matrix_sync(af, &Hs[r0 * 132 + kk * 8], 132);
            wmma::load_matrix_sync(bf0, &W1s[kk * 8 * 36], 36);
            wmma::load_matrix_sync(bf1, &W1s[kk * 8 * 36 + 16], 36);
            wmma::mma_sync(oacc[0], af, bf0, oacc[0]);
            wmma::mma_sync(oacc[1], af, bf1, oacc[1]);
        }
        float* dst = g_part + (size_t)p * MROWS * 32 + (size_t)(m0 + r0) * 32;
        wmma::store_matrix_sync(dst, oacc[0], 32, wmma::mem_row_major);
        wmma::store_matrix_sync(dst + 16, oacc[1], 32, wmma::mem_row_major);
    }
}

// ---------------------------------------------------------------------------
// STAGE2 v3 (round-12 best): 4-view weight sharing, combine fused,
// bf0w/gf0w/rd1w from GLOBAL, 3 CTAs/SM.
// ---------------------------------------------------------------------------
struct WPtrs { const float* p[20]; };

#define WTOT    6228
#define WARPTMP 1208

__global__ void __launch_bounds__(256, 3) stage2_kernel(
    const float* __restrict__ tokG, const void* __restrict__ invG,
    const float* __restrict__ rdiff, WPtrs wp,
    const float* __restrict__ rd0w_, const float* __restrict__ rd0b_,
    const float* __restrict__ rd1w_, const float* __restrict__ rd1b_,
    const float* __restrict__ b1_, float* __restrict__ out)
{
    extern __shared__ float sm[];
    const int tid = threadIdx.x, wid = tid >> 5, lane = tid & 31;

    const int srcidx[18] = {0,1,2,3,5,6,7,8,9,10,11,12,13,14,15,17,18,19};
    const int cnt[18] = {128,8,8,1,64,2048,32,1024,32,1056,33,1024,32,32,1,32,512,16};
    const int off[18] = {0,128,136,144,145,209,2257,2289,3313,3345,4401,4434,5458,5490,5522,5523,5555,6067};
    for (int s = 0; s < 18; s++) {
        const float* src = wp.p[srcidx[s]]; float* dst = sm + off[s];
        for (int i = tid; i < cnt[s]; i += 256) dst[i] = src[i];
    }
    for (int i = tid; i < 64; i += 256) sm[6083 + i] = rd0w_[i];
    for (int i = tid; i < 16; i += 256) sm[6147 + i] = rd0b_[i];
    for (int i = tid; i < 32; i += 256) sm[6163 + i] = rd1b_[i];
    for (int i = tid; i < 32; i += 256) sm[6195 + i] = b1_[i];
    __syncthreads();

    const float* nr0w = sm;          const float* nr0b = sm + 128;
    const float* nr1w = sm + 136;    const float* nr1b = sm + 144;
    const float* bf0wg = wp.p[4];    // GLOBAL
    const float* bf0b = sm + 145;
    const float* bf1w = sm + 209;    const float* bf1b = sm + 2257;
    const float* vf0w = sm + 2289;   const float* vf0b = sm + 3313;
    const float* vf1w = sm + 3345;   const float* vf1b = sm + 4401;
    const float* v20w = sm + 4434;   const float* v20b = sm + 5458;
    const float* v21w = sm + 5490;   const float* v21b = sm + 5522;
    const float* gf0wg = wp.p[16];   // GLOBAL
    const float* gf0b = sm + 5523;
    const float* gf1w = sm + 5555;   const float* gf1b = sm + 6067;
    const float* rd0w = sm + 6083;   const float* rd0b = sm + 6147;
    const float* rd1b = sm + 6163;   const float* b1s  = sm + 6195;

    float* T = sm + WTOT + wid * WARPTMP;
    float* tokW = T;          float* bottW = T + 128;  float* xW   = T + 384;
    float* gfW  = T + 640;    float* h256  = T + 768;  float* h33q = T + 1024;
    float* wtW  = T + 1168;   float* w0W   = T + 1176; float* mskW = T + 1184;
    float* visW = T + 1192;   float* w2W   = T + 1200;

    int t = blockIdx.x * 8 + wid;

    const unsigned char* bb = (const unsigned char*)invG;
    int u8f = 0;
    for (int i = lane; i < 256; i += 32) if ((i & 3) && bb[i] == 1) u8f = 1;
    u8f = (__ballot_sync(0xffffffffu, u8f) != 0);

    for (int i = lane; i < 128; i += 32) tokW[i] = tokG[(size_t)t * 128 + i];
    float mv = 0.f;
    if (lane < 8) {
        int idx = t * 8 + lane;
        bool inv = u8f ? (bb[idx] != 0)
                       : (((const unsigned int*)invG)[idx] != 0u);
        mv = inv ? 0.f : 1.f;
    }
    float msum = wrsum(mv);
    if (lane < 8) { mskW[lane] = mv; wtW[lane] = mv / (msum + 1e-8f); }

#pragma unroll
    for (int vp = 0; vp < 4; vp++) {
        size_t rA = (size_t)t * 8 + 2 * vp, rB = rA + 1;
        float rvA = (lane < 4) ? rdiff[rA * 4 + lane] : 0.f;
        float rvB = (lane < 4) ? rdiff[rB * 4 + lane] : 0.f;
        float a0 = __shfl_sync(0xffffffffu, rvA, 0), a1 = __shfl_sync(0xffffffffu, rvA, 1);
        float a2 = __shfl_sync(0xffffffffu, rvA, 2), a3 = __shfl_sync(0xffffffffu, rvA, 3);
        float c0 = __shfl_sync(0xffffffffu, rvB, 0), c1 = __shfl_sync(0xffffffffu, rvB, 1);
        float c2 = __shfl_sync(0xffffffffu, rvB, 2), c3 = __shfl_sync(0xffffffffu, rvB, 3);
        float h0 = 0.f, h1 = 0.f;
        if (lane < 16) {
            h0 = eluf(rd0b[lane] + a0 * rd0w[lane] + a1 * rd0w[16 + lane]
                                 + a2 * rd0w[32 + lane] + a3 * rd0w[48 + lane]);
            h1 = eluf(rd0b[lane] + c0 * rd0w[lane] + c1 * rd0w[16 + lane]
                                 + c2 * rd0w[32 + lane] + c3 * rd0w[48 + lane]);
        }
        float d0 = rd1b[lane], d1 = rd1b[lane];
#pragma unroll
        for (int k = 0; k < 16; k++) {
            float w = __ldg(&rd1w_[k * 32 + lane]);
            d0 += __shfl_sync(0xffffffffu, h0, k) * w;
            d1 += __shfl_sync(0xffffffffu, h1, k) * w;
        }
        float s0 = b1s[lane] + eluf(d0), s1 = b1s[lane] + eluf(d1);
#pragma unroll
        for (int p = 0; p < 4; p++) {
            s0 += g_part[(size_t)p * MROWS * 32 + rA * 32 + lane];
            s1 += g_part[(size_t)p * MROWS * 32 + rB * 32 + lane];
        }
        bottW[2 * vp * 32 + lane] = s0;
        bottW[(2 * vp + 1) * 32 + lane] = s1;
    }
    __syncwarp();

    if (lane < 8) {
        float hh[8];
#pragma unroll
        for (int i = 0; i < 8; i++) hh[i] = nr0b[i];
#pragma unroll
        for (int k = 0; k < 16; k++) {
            float tv = tokW[lane * 16 + k];
#pragma unroll
            for (int i = 0; i < 8; i++) hh[i] += tv * nr0w[k * 8 + i];
        }
        float s = nr1b[0];
#pragma unroll
        for (int i = 0; i < 8; i++) s += eluf(hh[i]) * nr1w[i];
        w0W[lane] = sigm(s) * wtW[lane];
    }
    __syncwarp();

    {
        float m0 = 0.f, m1 = 0.f;
#pragma unroll
        for (int v = 0; v < 8; v++) { float b = bottW[v * 32 + lane]; m0 += b * w0W[v]; m1 += b * wtW[v]; }
        float v0 = 0.f, v1 = 0.f;
#pragma unroll
        for (int v = 0; v < 8; v++) {
            float b = bottW[v * 32 + lane]; float d0 = b - m0, d1 = b - m1;
            v0 += w0W[v] * d0 * d0; v1 += wtW[v] * d1 * d1;
        }
        gfW[lane] = m0; gfW[32 + lane] = v0; gfW[64 + lane] = m1; gfW[96 + lane] = v1;
    }
    __syncwarp();

    float gfc0 = bf0b[lane], gfc1 = bf0b[32 + lane];
#pragma unroll
    for (int k4 = 0; k4 < 32; k4++) {
        float4 g4 = *(float4*)&gfW[k4 * 4];
#pragma unroll
        for (int e = 0; e < 4; e++) {
            int k = k4 * 4 + e;
            float g = (&g4.x)[e];
            gfc0 += g * __ldg(&bf0wg[k * 64 + lane]);
            gfc1 += g * __ldg(&bf0wg[k * 64 + 32 + lane]);
        }
    }

#pragma unroll 1
    for (int sp = 0; sp < 2; sp++) {
        const int vb = sp * 4;
        float a0[4], a1[4];
#pragma unroll
        for (int v = 0; v < 4; v++) { a0[v] = gfc0; a1[v] = gfc1; }
#pragma unroll
        for (int k4 = 0; k4 < 8; k4++) {
            float4 bv[4];
#pragma unroll
            for (int v = 0; v < 4; v++) bv[v] = *(float4*)&bottW[(vb + v) * 32 + k4 * 4];
#pragma unroll
            for (int e = 0; e < 4; e++) {
                int k = k4 * 4 + e;
                float w0 = __ldg(&bf0wg[(128 + k) * 64 + lane]);
                float w1 = __ldg(&bf0wg[(128 + k) * 64 + 32 + lane]);
#pragma unroll
                for (int v = 0; v < 4; v++) {
                    float f = (&bv[v].x)[e];
                    a0[v] += f * w0; a1[v] += f * w1;
                }
            }
        }
#pragma unroll
        for (int k4 = 0; k4 < 4; k4++) {
            float4 tv4[4];
#pragma unroll
            for (int v = 0; v < 4; v++) tv4[v] = *(float4*)&tokW[(vb + v) * 16 + k4 * 4];
#pragma unroll
            for (int e = 0; e < 4; e++) {
                int k = k4 * 4 + e;
                float w0 = __ldg(&bf0wg[(160 + k) * 64 + lane]);
                float w1 = __ldg(&bf0wg[(160 + k) * 64 + 32 + lane]);
#pragma unroll
                for (int v = 0; v < 4; v++) {
                    float f = (&tv4[v].x)[e];
                    a0[v] += f * w0; a1[v] += f * w1;
                }
            }
        }
#pragma unroll
        for (int v = 0; v < 4; v++) {
            h256[v * 64 + lane] = eluf(a0[v]);
            h256[v * 64 + 32 + lane] = eluf(a1[v]);
        }
        __syncwarp();
        {
            float s[4];
#pragma unroll
            for (int v = 0; v < 4; v++) s[v] = bf1b[lane];
#pragma unroll
            for (int k4 = 0; k4 < 16; k4++) {
                float4 hv[4];
#pragma unroll
                for (int v = 0; v < 4; v++) hv[v] = *(float4*)&h256[v * 64 + k4 * 4];
#pragma unroll
                for (int e = 0; e < 4; e++) {
                    float w = bf1w[(k4 * 4 + e) * 32 + lane];
#pragma unroll
                    for (int v = 0; v < 4; v++) s[v] += (&hv[v].x)[e] * w;
                }
            }
#pragma unroll
            for (int v = 0; v < 4; v++) xW[(vb + v) * 32 + lane] = eluf(s[v]);
        }
        __syncwarp();
        {
            float dot[4] = {0.f, 0.f, 0.f, 0.f};
#pragma unroll
            for (int k4 = 0; k4 < 8; k4++) {
                float4 xv[4];
#pragma unroll
                for (int v = 0; v < 4; v++) xv[v] = *(float4*)&xW[(vb + v) * 32 + k4 * 4];
#pragma unroll
                for (int e = 0; e < 4; e++) {
                    float w = vf0w[(k4 * 4 + e) * 32 + lane];
#pragma unroll
                    for (int v = 0; v < 4; v++) dot[v] += (&xv[v].x)[e] * w;
                }
            }
#pragma unroll
            for (int v = 0; v < 4; v++)
                h33q[v * 36 + lane] = eluf(vf0b[lane] + wtW[vb + v] * dot[v]);
        }
        __syncwarp();
        float xr[4];
        {
#pragma unroll
            for (int v = 0; v < 4; v++) xr[v] = vf1b[lane];
#pragma unroll
            for (int k4 = 0; k4 < 8; k4++) {
                float4 hq[4];
#pragma unroll
                for (int v = 0; v < 4; v++) hq[v] = *(float4*)&h33q[v * 36 + k4 * 4];
#pragma unroll
                for (int e = 0; e < 4; e++) {
                    float w = vf1w[(k4 * 4 + e) * 33 + lane];
#pragma unroll
                    for (int v = 0; v < 4; v++) xr[v] += (&hq[v].x)[e] * w;
                }
            }
#pragma unroll
            for (int v = 0; v < 4; v++) xr[v] = eluf(xr[v]);
        }
        if (lane < 4) {
            const float* hx = &h33q[lane * 36];
            float a = vf1b[32];
#pragma unroll
            for (int k = 0; k < 32; k++) a += hx[k] * vf1w[k * 33 + 32];
            visW[vb + lane] = sigm(eluf(a)) * mskW[vb + lane];
        }
        __syncwarp();
#pragma unroll
        for (int v = 0; v < 4; v++) xW[(vb + v) * 32 + lane] += xr[v];
        __syncwarp();
        {
            float dot[4] = {0.f, 0.f, 0.f, 0.f};
#pragma unroll
            for (int k4 = 0; k4 < 8; k4++) {
                float4 xv[4];
#pragma unroll
                for (int v = 0; v < 4; v++) xv[v] = *(float4*)&xW[(vb + v) * 32 + k4 * 4];
#pragma unroll
                for (int e = 0; e < 4; e++) {
                    float w = v20w[(k4 * 4 + e) * 32 + lane];
#pragma unroll
                    for (int v = 0; v < 4; v++) dot[v] += (&xv[v].x)[e] * w;
                }
            }
#pragma unroll
            for (int v = 0; v < 4; v++)
                h33q[v * 36 + lane] = eluf(v20b[lane] + visW[vb + v] * dot[v]);
        }
        __syncwarp();
        {
            float wv21 = v21w[lane];
#pragma unroll
            for (int v = 0; v < 4; v++) {
                float s = wrsum(h33q[v * 36 + lane] * wv21) + v21b[0];
                if (lane == 0) w2W[vb + v] = sigm(s) * mskW[vb + v];
            }
        }
        __syncwarp();
    }

    {
        float vv = (lane < 8) ? w2W[lane] : 0.f;
        float s = wrsum(vv);
        if (lane < 8) w2W[lane] = vv / (s + 1e-8f);
    }
    __syncwarp();
    float wbar;
    {
        float vv = (lane < 8) ? w2W[lane] : 0.f;
        wbar = wrsum(vv) * 0.125f;
    }
    {
        float m = 0.f;
#pragma unroll
        for (int v = 0; v < 8; v++) m += xW[v * 32 + lane] * w2W[v];
        float va = 0.f;
#pragma unroll
        for (int v = 0; v < 8; v++) { float dd = xW[v * 32 + lane] - m; va += w2W[v] * dd * dd; }
        gfW[lane] = m; gfW[32 + lane] = va;
        if (lane == 0) gfW[64] = wbar;
    }
    __syncwarp();
    {
        float a = gf0b[lane];
#pragma unroll
        for (int k4 = 0; k4 < 16; k4++) {
            float4 g4 = *(float4*)&gfW[k4 * 4];
#pragma unroll
            for (int e = 0; e < 4; e++)
                a += (&g4.x)[e] * __ldg(&gf0wg[(k4 * 4 + e) * 32 + lane]);
        }
        a += gfW[64] * __ldg(&gf0wg[64 * 32 + lane]);
        h33q[lane] = eluf(a);
    }
    __syncwarp();
    if (lane < 16) {
        float a = gf1b[lane];
#pragma unroll
        for (int k = 0; k < 32; k++) a += h33q[k] * gf1w[k * 16 + lane];
        out[(size_t)t * 16 + lane] = eluf(a);
    }
}

// ---------------------------------------------------------------------------
extern "C" void kernel_launch(void* const* d_in, const int* in_sizes, int n_in,
                              void* d_out, int out_size)
{
    const float* tok   = (const float*)d_in[0];
    const float* bott  = (const float*)d_in[1];
    const float* rdiff = (const float*)d_in[2];
    const void*  inval = (const void*)d_in[3];
    const float* rd0w = (const float*)d_in[4];  const float* rd0b = (const float*)d_in[5];
    const float* rd1w = (const float*)d_in[6];  const float* rd1b = (const float*)d_in[7];
    const float* if0w = (const float*)d_in[8];  const float* if0b = (const float*)d_in[9];
    const float* if1w = (const float*)d_in[10]; const float* if1b = (const float*)d_in[11];
    float* out = (float*)d_out;

    WPtrs wp;
    for (int i = 0; i < 20; i++) wp.p[i] = (const float*)d_in[12 + i];

    const int stage2_smem = (WTOT + 8 * WARPTMP) * 4;   // 63568 B -> 3 CTAs/SM
    cudaFuncSetAttribute(gemm1_kernel, cudaFuncAttributeMaxDynamicSharedMemorySize, SMEM_G1);
    cudaFuncSetAttribute(stage2_kernel, cudaFuncAttributeMaxDynamicSharedMemorySize, stage2_smem);

    prep_w0t<<<dim3(16, 64), dim3(32, 8)>>>(if0w);
    gemm1_kernel<<<dim3(4, 1024), 256, SMEM_G1>>>(bott, if0b, if1w);
    stage2_kernel<<<TOTPTS / 8, 256, stage2_smem>>>(tok, inval, rdiff, wp,
                                                    rd0w, rd0b, rd1w, rd1b, if1b, out);
}

// round 15
// speedup vs baseline: 1.5531x; 1.5531x over previous
#include <cuda_runtime.h>
#include <mma.h>
#include <math.h>
#include <stdint.h>

using namespace nvcuda;

#define TOTPTS 16384
#define MROWS  131072   // TOT*NV
#define KDIM   2048
#define NDIM   512

// Static device scratch (no runtime allocation allowed).
__device__ float g_W0T[(size_t)NDIM * KDIM];       // W0^T [n][k], tf32-RN, 4MB
__device__ float g_part[(size_t)4 * MROWS * 32];   // per-N-chunk partial B32, 64MB

__device__ __forceinline__ float eluf(float x) { return x > 0.f ? x : expm1f(x); }
__device__ __forceinline__ float sigm(float x) { return 1.f / (1.f + expf(-x)); }
__device__ __forceinline__ float wrsum(float v) {
#pragma unroll
    for (int o = 16; o > 0; o >>= 1) v += __shfl_xor_sync(0xffffffffu, v, o);
    return v;
}
__device__ __forceinline__ float rnd_tf32(float x) {
    float r;
    asm("cvt.rna.tf32.f32 %0, %1;" : "=f"(r) : "f"(x));
    return r;
}
__device__ __forceinline__ uint32_t smem_u32(const void* p) {
    uint32_t a;
    asm("{ .reg .u64 t; cvta.to.shared.u64 t, %1; cvt.u32.u64 %0, t; }" : "=r"(a) : "l"(p));
    return a;
}
__device__ __forceinline__ void bulkcp(uint32_t dst, const void* src, uint32_t bytes,
                                       uint32_t bar) {
    asm volatile("cp.async.bulk.shared::cta.global.mbarrier::complete_tx::bytes "
                 "[%0], [%1], %2, [%3];"
                 :: "r"(dst), "l"(src), "r"(bytes), "r"(bar) : "memory");
}
__device__ __forceinline__ void ldsm4(uint32_t& r0, uint32_t& r1, uint32_t& r2, uint32_t& r3,
                                      uint32_t addr) {
    asm volatile("ldmatrix.sync.aligned.m8n8.x4.shared.b16 {%0,%1,%2,%3}, [%4];"
                 : "=r"(r0), "=r"(r1), "=r"(r2), "=r"(r3) : "r"(addr));
}
__device__ __forceinline__ void mma8(float* d, const uint32_t* a, const uint32_t* b) {
    asm volatile("mma.sync.aligned.m16n8k8.row.col.f32.tf32.tf32.f32 "
                 "{%0,%1,%2,%3}, {%4,%5,%6,%7}, {%8,%9}, {%0,%1,%2,%3};"
                 : "+f"(d[0]), "+f"(d[1]), "+f"(d[2]), "+f"(d[3])
                 : "r"(a[0]), "r"(a[1]), "r"(a[2]), "r"(a[3]), "r"(b[0]), "r"(b[1]));
}
#define MBAR_INIT(a, c) asm volatile("mbarrier.init.shared.b64 [%0], %1;" :: "r"(a), "r"(c) : "memory")
#define MBAR_EXPECT(a, tx) asm volatile("mbarrier.arrive.expect_tx.shared.b64 _, [%0], %1;" :: "r"(a), "r"(tx) : "memory")
#define MBAR_WAIT(a, ph) do {                                                              \
    uint32_t _m = (a), _p = (ph), _d;                                                      \
    asm volatile("{\n\t.reg .pred p;\n\t"                                                  \
                 "mbarrier.try_wait.parity.acquire.cta.shared::cta.b64 p, [%1], %2;\n\t"   \
                 "selp.b32 %0, 1, 0, p;\n\t}" : "=r"(_d) : "r"(_m), "r"(_p) : "memory");   \
    if (!_d) {                                                                             \
        asm volatile("{\n\t.reg .pred P1;\n\t"                                             \
            "WL%=:\n\t"                                                                    \
            "mbarrier.try_wait.parity.acquire.cta.shared::cta.b64 P1, [%0], %1, 0x989680;\n\t" \
            "@P1 bra.uni WD%=;\n\t"                                                        \
            "bra.uni WL%=;\n\t"                                                            \
            "WD%=:\n\t}" :: "r"(_m), "r"(_p) : "memory");                                  \
    }                                                                                      \
} while (0)
#define FENCE_PROXY() asm volatile("fence.proxy.async.shared::cta;" ::: "memory")

// ---------------------------------------------------------------------------
// PREP: g_W0T[n][k] = rn_tf32(W0[k][n])
// ---------------------------------------------------------------------------
__global__ void prep_w0t(const float* __restrict__ W0) {
    __shared__ float tile[32][33];
    int n0 = blockIdx.x * 32, k0 = blockIdx.y * 32;
    int tx = threadIdx.x, ty = threadIdx.y;
#pragma unroll
    for (int j = 0; j < 32; j += 8)
        tile[ty + j][tx] = W0[(size_t)(k0 + ty + j) * NDIM + n0 + tx];
    __syncthreads();
#pragma unroll
    for (int j = 0; j < 32; j += 8)
        g_W0T[(size_t)(n0 + ty + j) * KDIM + k0 + tx] = rnd_tf32(tile[tx][ty + j]);
}

// ---------------------------------------------------------------------------
// GEMM1 (at legacy tensor-pipe ceiling — verified rt16 model; unchanged).
// ---------------------------------------------------------------------------
#define STAGEB   36864
#define SMEM_G1  88064
#define HS_F     256
#define W1S_F    17152

__global__ void __launch_bounds__(256, 2) gemm1_kernel(
    const float* __restrict__ X, const float* __restrict__ b0,
    const float* __restrict__ W1)
{
    extern __shared__ float sm[];
    const uint32_t smem = smem_u32(sm);
    const int tid = threadIdx.x, wid = tid >> 5, lane = tid & 31;
    const int p = blockIdx.x, m0 = blockIdx.y * 128, n0 = p * 128;
    const int wm = (wid >> 2) * 64, wn = (wid & 3) * 32;

    if (tid < 128) sm[32 + tid] = b0[n0 + tid];
    if (tid == 0) {
        MBAR_INIT(smem + 16, 1);
        MBAR_INIT(smem + 24, 1);
        FENCE_PROXY();
    }
    __syncthreads();

    const bool isA = tid < 128;
    const int row = tid & 127;
    const float* srcbase = isA ? (X + (size_t)(m0 + row) * KDIM)
                               : (g_W0T + (size_t)(n0 + row) * KDIM);
    const uint32_t dsto = (isA ? 0u : 18432u) + (uint32_t)row * 144u;

    float acc[4][4][4];
#pragma unroll
    for (int g = 0; g < 4; g++)
#pragma unroll
        for (int j = 0; j < 4; j++)
#pragma unroll
            for (int e = 0; e < 4; e++) acc[g][j][e] = 0.f;

    const int rA = lane & 15, hA = (lane >> 4) & 1;
    const int rB = (lane & 7) + ((lane >> 4) & 1) * 8, hB = (lane >> 3) & 1;
    const uint32_t aoff = (uint32_t)(wm + rA) * 144u + (uint32_t)hA * 16u;
    const uint32_t boff = 18432u + (uint32_t)(wn + rB) * 144u + (uint32_t)hB * 16u;

#pragma unroll
    for (int t = 0; t < 2; t++) {
        uint32_t bar = smem + 16 + 8 * t;
        if (tid == 0) MBAR_EXPECT(bar, 32768);
        __syncwarp();
        bulkcp(smem + 1024 + t * STAGEB + dsto, srcbase + t * 32, 128, bar);
    }

    for (int t = 0; t < 64; t++) {
        const int s = t & 1;
        MBAR_WAIT(smem + 16 + 8 * s, (t >> 1) & 1);

        const uint32_t base = smem + 1024 + s * STAGEB;
#pragma unroll
        for (int ks = 0; ks < 4; ks++) {
            uint32_t a[4][4], b[2][4];
#pragma unroll
            for (int g = 0; g < 4; g++)
                ldsm4(a[g][0], a[g][1], a[g][2], a[g][3],
                      base + aoff + (uint32_t)g * 2304u + (uint32_t)ks * 32u);
#pragma unroll
            for (int jj = 0; jj < 2; jj++)
                ldsm4(b[jj][0], b[jj][1], b[jj][2], b[jj][3],
                      base + boff + (uint32_t)jj * 2304u + (uint32_t)ks * 32u);
#pragma unroll
            for (int g = 0; g < 4; g++)
#pragma unroll
                for (int e = 0; e < 4; e++)
                    a[g][e] = __float_as_uint(rnd_tf32(__uint_as_float(a[g][e])));
#pragma unroll
            for (int g = 0; g < 4; g++) {
                mma8(acc[g][0], a[g], &b[0][0]);
                mma8(acc[g][1], a[g], &b[0][2]);
                mma8(acc[g][2], a[g], &b[1][0]);
                mma8(acc[g][3], a[g], &b[1][2]);
            }
        }
        __syncthreads();
        if (t + 2 < 64) {
            uint32_t bar = smem + 16 + 8 * s;
            if (tid == 0) MBAR_EXPECT(bar, 32768);
            bulkcp(smem + 1024 + s * STAGEB + dsto, srcbase + (t + 2) * 32, 128, bar);
        }
    }

    float* Hs  = sm + HS_F;
    float* W1s = sm + W1S_F;
    {
        const int tr = lane >> 2, tc = 2 * (lane & 3);
#pragma unroll
        for (int g = 0; g < 4; g++)
#pragma unroll
            for (int j = 0; j < 4; j++) {
                int R0 = wm + g * 16 + tr, C = wn + j * 8 + tc;
                float b0c0 = sm[32 + C], b0c1 = sm[32 + C + 1];
                float2 v0, v1;
                v0.x = rnd_tf32(eluf(acc[g][j][0] + b0c0));
                v0.y = rnd_tf32(eluf(acc[g][j][1] + b0c1));
                v1.x = rnd_tf32(eluf(acc[g][j][2] + b0c0));
                v1.y = rnd_tf32(eluf(acc[g][j][3] + b0c1));
                *(float2*)&Hs[R0 * 132 + C] = v0;
                *(float2*)&Hs[(R0 + 8) * 132 + C] = v1;
            }
    }
    for (int i = tid; i < 128 * 32; i += 256) {
        int r = i >> 5, c = i & 31;
        W1s[r * 36 + c] = rnd_tf32(W1[(size_t)(n0 + r) * 32 + c]);
    }
    __syncthreads();

    {
        int r0 = wid * 16;
        wmma::fragment<wmma::accumulator, 16, 16, 8, float> oacc[2];
        wmma::fill_fragment(oacc[0], 0.f);
        wmma::fill_fragment(oacc[1], 0.f);
#pragma unroll
        for (int kk = 0; kk < 16; kk++) {
            wmma::fragment<wmma::matrix_a, 16, 16, 8, wmma::precision::tf32, wmma::row_major> af;
            wmma::fragment<wmma::matrix_b, 16, 16, 8, wmma::precision::tf32, wmma::row_major> bf0, bf1;
            wmma::load_matrix_sync(af, &Hs[r0 * 132 + kk * 8], 132);
            wmma::load_matrix_sync(bf0, &W1s[kk * 8 * 36], 36);
            wmma::load_matrix_sync(bf1, &W1s[kk * 8 * 36 + 16], 36);
            wmma::mma_sync(oacc[0], af, bf0, oacc[0]);
            wmma::mma_sync(oacc[1], af, bf1, oacc[1]);
        }
        float* dst = g_part + (size_t)p * MROWS * 32 + (size_t)(m0 + r0) * 32;
        wmma::store_matrix_sync(dst, oacc[0], 32, wmma::mem_row_major);
        wmma::store_matrix_sync(dst + 16, oacc[1], 32, wmma::mem_row_major);
    }
}

// ---------------------------------------------------------------------------
// STAGE2 v3 (round-12 best): 4-view weight sharing, combine fused,
// bf0w/gf0w/rd1w from GLOBAL, 3 CTAs/SM.
// ---------------------------------------------------------------------------
struct WPtrs { const float* p[20]; };

#define WTOT    6228
#define WARPTMP 1208

__global__ void __launch_bounds__(256, 3) stage2_kernel(
    const float* __restrict__ tokG, const void* __restrict__ invG,
    const float* __restrict__ rdiff, WPtrs wp,
    const float* __restrict__ rd0w_, const float* __restrict__ rd0b_,
    const float* __restrict__ rd1w_, const float* __restrict__ rd1b_,
    const float* __restrict__ b1_, float* __restrict__ out)
{
    extern __shared__ float sm[];
    const int tid = threadIdx.x, wid = tid >> 5, lane = tid & 31;

    const int srcidx[18] = {0,1,2,3,5,6,7,8,9,10,11,12,13,14,15,17,18,19};
    const int cnt[18] = {128,8,8,1,64,2048,32,1024,32,1056,33,1024,32,32,1,32,512,16};
    const int off[18] = {0,128,136,144,145,209,2257,2289,3313,3345,4401,4434,5458,5490,5522,5523,5555,6067};
    for (int s = 0; s < 18; s++) {
        const float* src = wp.p[srcidx[s]]; float* dst = sm + off[s];
        for (int i = tid; i < cnt[s]; i += 256) dst[i] = src[i];
    }
    for (int i = tid; i < 64; i += 256) sm[6083 + i] = rd0w_[i];
    for (int i = tid; i < 16; i += 256) sm[6147 + i] = rd0b_[i];
    for (int i = tid; i < 32; i += 256) sm[6163 + i] = rd1b_[i];
    for (int i = tid; i < 32; i += 256) sm[6195 + i] = b1_[i];
    __syncthreads();

    const float* nr0w = sm;          const float* nr0b = sm + 128;
    const float* nr1w = sm + 136;    const float* nr1b = sm + 144;
    const float* bf0wg = wp.p[4];    // GLOBAL
    const float* bf0b = sm + 145;
    const float* bf1w = sm + 209;    const float* bf1b = sm + 2257;
    const float* vf0w = sm + 2289;   const float* vf0b = sm + 3313;
    const float* vf1w = sm + 3345;   const float* vf1b = sm + 4401;
    const float* v20w = sm + 4434;   const float* v20b = sm + 5458;
    const float* v21w = sm + 5490;   const float* v21b = sm + 5522;
    const float* gf0wg = wp.p[16];   // GLOBAL
    const float* gf0b = sm + 5523;
    const float* gf1w = sm + 5555;   const float* gf1b = sm + 6067;
    const float* rd0w = sm + 6083;   const float* rd0b = sm + 6147;
    const float* rd1b = sm + 6163;   const float* b1s  = sm + 6195;

    float* T = sm + WTOT + wid * WARPTMP;
    float* tokW = T;          float* bottW = T + 128;  float* xW   = T + 384;
    float* gfW  = T + 640;    float* h256  = T + 768;  float* h33q = T + 1024;
    float* wtW  = T + 1168;   float* w0W   = T + 1176; float* mskW = T + 1184;
    float* visW = T + 1192;   float* w2W   = T + 1200;

    int t = blockIdx.x * 8 + wid;

    const unsigned char* bb = (const unsigned char*)invG;
    int u8f = 0;
    for (int i = lane; i < 256; i += 32) if ((i & 3) && bb[i] == 1) u8f = 1;
    u8f = (__ballot_sync(0xffffffffu, u8f) != 0);

    for (int i = lane; i < 128; i += 32) tokW[i] = tokG[(size_t)t * 128 + i];
    float mv = 0.f;
    if (lane < 8) {
        int idx = t * 8 + lane;
        bool inv = u8f ? (bb[idx] != 0)
                       : (((const unsigned int*)invG)[idx] != 0u);
        mv = inv ? 0.f : 1.f;
    }
    float msum = wrsum(mv);
    if (lane < 8) { mskW[lane] = mv; wtW[lane] = mv / (msum + 1e-8f); }

#pragma unroll
    for (int vp = 0; vp < 4; vp++) {
        size_t rA = (size_t)t * 8 + 2 * vp, rB = rA + 1;
        float rvA = (lane < 4) ? rdiff[rA * 4 + lane] : 0.f;
        float rvB = (lane < 4) ? rdiff[rB * 4 + lane] : 0.f;
        float a0 = __shfl_sync(0xffffffffu, rvA, 0), a1 = __shfl_sync(0xffffffffu, rvA, 1);
        float a2 = __shfl_sync(0xffffffffu, rvA, 2), a3 = __shfl_sync(0xffffffffu, rvA, 3);
        float c0 = __shfl_sync(0xffffffffu, rvB, 0), c1 = __shfl_sync(0xffffffffu, rvB, 1);
        float c2 = __shfl_sync(0xffffffffu, rvB, 2), c3 = __shfl_sync(0xffffffffu, rvB, 3);
        float h0 = 0.f, h1 = 0.f;
        if (lane < 16) {
            h0 = eluf(rd0b[lane] + a0 * rd0w[lane] + a1 * rd0w[16 + lane]
                                 + a2 * rd0w[32 + lane] + a3 * rd0w[48 + lane]);
            h1 = eluf(rd0b[lane] + c0 * rd0w[lane] + c1 * rd0w[16 + lane]
                                 + c2 * rd0w[32 + lane] + c3 * rd0w[48 + lane]);
        }
        float d0 = rd1b[lane], d1 = rd1b[lane];
#pragma unroll
        for (int k = 0; k < 16; k++) {
            float w = __ldg(&rd1w_[k * 32 + lane]);
            d0 += __shfl_sync(0xffffffffu, h0, k) * w;
            d1 += __shfl_sync(0xffffffffu, h1, k) * w;
        }
        float s0 = b1s[lane] + eluf(d0), s1 = b1s[lane] + eluf(d1);
#pragma unroll
        for (int p = 0; p < 4; p++) {
            s0 += g_part[(size_t)p * MROWS * 32 + rA * 32 + lane];
            s1 += g_part[(size_t)p * MROWS * 32 + rB * 32 + lane];
        }
        bottW[2 * vp * 32 + lane] = s0;
        bottW[(2 * vp + 1) * 32 + lane] = s1;
    }
    __syncwarp();

    if (lane < 8) {
        float hh[8];
#pragma unroll
        for (int i = 0; i < 8; i++) hh[i] = nr0b[i];
#pragma unroll
        for (int k = 0; k < 16; k++) {
            float tv = tokW[lane * 16 + k];
#pragma unroll
            for (int i = 0; i < 8; i++) hh[i] += tv * nr0w[k * 8 + i];
        }
        float s = nr1b[0];
#pragma unroll
        for (int i = 0; i < 8; i++) s += eluf(hh[i]) * nr1w[i];
        w0W[lane] = sigm(s) * wtW[lane];
    }
    __syncwarp();

    {
        float m0 = 0.f, m1 = 0.f;
#pragma unroll
        for (int v = 0; v < 8; v++) { float b = bottW[v * 32 + lane]; m0 += b * w0W[v]; m1 += b * wtW[v]; }
        float v0 = 0.f, v1 = 0.f;
#pragma unroll
        for (int v = 0; v < 8; v++) {
            float b = bottW[v * 32 + lane]; float d0 = b - m0, d1 = b - m1;
            v0 += w0W[v] * d0 * d0; v1 += wtW[v] * d1 * d1;
        }
        gfW[lane] = m0; gfW[32 + lane] = v0; gfW[64 + lane] = m1; gfW[96 + lane] = v1;
    }
    __syncwarp();

    float gfc0 = bf0b[lane], gfc1 = bf0b[32 + lane];
#pragma unroll
    for (int k4 = 0; k4 < 32; k4++) {
        float4 g4 = *(float4*)&gfW[k4 * 4];
#pragma unroll
        for (int e = 0; e < 4; e++) {
            int k = k4 * 4 + e;
            float g = (&g4.x)[e];
            gfc0 += g * __ldg(&bf0wg[k * 64 + lane]);
            gfc1 += g * __ldg(&bf0wg[k * 64 + 32 + lane]);
        }
    }

#pragma unroll 1
    for (int sp = 0; sp < 2; sp++) {
        const int vb = sp * 4;
        float a0[4], a1[4];
#pragma unroll
        for (int v = 0; v < 4; v++) { a0[v] = gfc0; a1[v] = gfc1; }
#pragma unroll
        for (int k4 = 0; k4 < 8; k4++) {
            float4 bv[4];
#pragma unroll
            for (int v = 0; v < 4; v++) bv[v] = *(float4*)&bottW[(vb + v) * 32 + k4 * 4];
#pragma unroll
            for (int e = 0; e < 4; e++) {
                int k = k4 * 4 + e;
                float w0 = __ldg(&bf0wg[(128 + k) * 64 + lane]);
                float w1 = __ldg(&bf0wg[(128 + k) * 64 + 32 + lane]);
#pragma unroll
                for (int v = 0; v < 4; v++) {
                    float f = (&bv[v].x)[e];
                    a0[v] += f * w0; a1[v] += f * w1;
                }
            }
        }
#pragma unroll
        for (int k4 = 0; k4 < 4; k4++) {
            float4 tv4[4];
#pragma unroll
            for (int v = 0; v < 4; v++) tv4[v] = *(float4*)&tokW[(vb + v) * 16 + k4 * 4];
#pragma unroll
            for (int e = 0; e < 4; e++) {
                int k = k4 * 4 + e;
                float w0 = __ldg(&bf0wg[(160 + k) * 64 + lane]);
                float w1 = __ldg(&bf0wg[(160 + k) * 64 + 32 + lane]);
#pragma unroll
                for (int v = 0; v < 4; v++) {
                    float f = (&tv4[v].x)[e];
                    a0[v] += f * w0; a1[v] += f * w1;
                }
            }
        }
#pragma unroll
        for (int v = 0; v < 4; v++) {
            h256[v * 64 + lane] = eluf(a0[v]);
            h256[v * 64 + 32 + lane] = eluf(a1[v]);
        }
        __syncwarp();
        {
            float s[4];
#pragma unroll
            for (int v = 0; v < 4; v++) s[v] = bf1b[lane];
#pragma unroll
            for (int k4 = 0; k4 < 16; k4++) {
                float4 hv[4];
#pragma unroll
                for (int v = 0; v < 4; v++) hv[v] = *(float4*)&h256[v * 64 + k4 * 4];
#pragma unroll
                for (int e = 0; e < 4; e++) {
                    float w = bf1w[(k4 * 4 + e) * 32 + lane];
#pragma unroll
                    for (int v = 0; v < 4; v++) s[v] += (&hv[v].x)[e] * w;
                }
            }
#pragma unroll
            for (int v = 0; v < 4; v++) xW[(vb + v) * 32 + lane] = eluf(s[v]);
        }
        __syncwarp();
        {
            float dot[4] = {0.f, 0.f, 0.f, 0.f};
#pragma unroll
            for (int k4 = 0; k4 < 8; k4++) {
                float4 xv[4];
#pragma unroll
                for (int v = 0; v < 4; v++) xv[v] = *(float4*)&xW[(vb + v) * 32 + k4 * 4];
#pragma unroll
                for (int e = 0; e < 4; e++) {
                    float w = vf0w[(k4 * 4 + e) * 32 + lane];
#pragma unroll
                    for (int v = 0; v < 4; v++) dot[v] += (&xv[v].x)[e] * w;
                }
            }
#pragma unroll
            for (int v = 0; v < 4; v++)
                h33q[v * 36 + lane] = eluf(vf0b[lane] + wtW[vb + v] * dot[v]);
        }
        __syncwarp();
        float xr[4];
        {
#pragma unroll
            for (int v = 0; v < 4; v++) xr[v] = vf1b[lane];
#pragma unroll
            for (int k4 = 0; k4 < 8; k4++) {
                float4 hq[4];
#pragma unroll
                for (int v = 0; v < 4; v++) hq[v] = *(float4*)&h33q[v * 36 + k4 * 4];
#pragma unroll
                for (int e = 0; e < 4; e++) {
                    float w = vf1w[(k4 * 4 + e) * 33 + lane];
#pragma unroll
                    for (int v = 0; v < 4; v++) xr[v] += (&hq[v].x)[e] * w;
                }
            }
#pragma unroll
            for (int v = 0; v < 4; v++) xr[v] = eluf(xr[v]);
        }
        if (lane < 4) {
            const float* hx = &h33q[lane * 36];
            float a = vf1b[32];
#pragma unroll
            for (int k = 0; k < 32; k++) a += hx[k] * vf1w[k * 33 + 32];
            visW[vb + lane] = sigm(eluf(a)) * mskW[vb + lane];
        }
        __syncwarp();
#pragma unroll
        for (int v = 0; v < 4; v++) xW[(vb + v) * 32 + lane] += xr[v];
        __syncwarp();
        {
            float dot[4] = {0.f, 0.f, 0.f, 0.f};
#pragma unroll
            for (int k4 = 0; k4 < 8; k4++) {
                float4 xv[4];
#pragma unroll
                for (int v = 0; v < 4; v++) xv[v] = *(float4*)&xW[(vb + v) * 32 + k4 * 4];
#pragma unroll
                for (int e = 0; e < 4; e++) {
                    float w = v20w[(k4 * 4 + e) * 32 + lane];
#pragma unroll
                    for (int v = 0; v < 4; v++) dot[v] += (&xv[v].x)[e] * w;
                }
            }
#pragma unroll
            for (int v = 0; v < 4; v++)
                h33q[v * 36 + lane] = eluf(v20b[lane] + visW[vb + v] * dot[v]);
        }
        __syncwarp();
        {
            float wv21 = v21w[lane];
#pragma unroll
            for (int v = 0; v < 4; v++) {
                float s = wrsum(h33q[v * 36 + lane] * wv21) + v21b[0];
                if (lane == 0) w2W[vb + v] = sigm(s) * mskW[vb + v];
            }
        }
        __syncwarp();
    }

    {
        float vv = (lane < 8) ? w2W[lane] : 0.f;
        float s = wrsum(vv);
        if (lane < 8) w2W[lane] = vv / (s + 1e-8f);
    }
    __syncwarp();
    float wbar;
    {
        float vv = (lane < 8) ? w2W[lane] : 0.f;
        wbar = wrsum(vv) * 0.125f;
    }
    {
        float m = 0.f;
#pragma unroll
        for (int v = 0; v < 8; v++) m += xW[v * 32 + lane] * w2W[v];
        float va = 0.f;
#pragma unroll
        for (int v = 0; v < 8; v++) { float dd = xW[v * 32 + lane] - m; va += w2W[v] * dd * dd; }
        gfW[lane] = m; gfW[32 + lane] = va;
        if (lane == 0) gfW[64] = wbar;
    }
    __syncwarp();
    {
        float a = gf0b[lane];
#pragma unroll
        for (int k4 = 0; k4 < 16; k4++) {
            float4 g4 = *(float4*)&gfW[k4 * 4];
#pragma unroll
            for (int e = 0; e < 4; e++)
                a += (&g4.x)[e] * __ldg(&gf0wg[(k4 * 4 + e) * 32 + lane]);
        }
        a += gfW[64] * __ldg(&gf0wg[64 * 32 + lane]);
        h33q[lane] = eluf(a);
    }
    __syncwarp();
    if (lane < 16) {
        float a = gf1b[lane];
#pragma unroll
        for (int k = 0; k < 32; k++) a += h33q[k] * gf1w[k * 16 + lane];
        out[(size_t)t * 16 + lane] = eluf(a);
    }
}

// ---------------------------------------------------------------------------
extern "C" void kernel_launch(void* const* d_in, const int* in_sizes, int n_in,
                              void* d_out, int out_size)
{
    const float* tok   = (const float*)d_in[0];
    const float* bott  = (const float*)d_in[1];
    const float* rdiff = (const float*)d_in[2];
    const void*  inval = (const void*)d_in[3];
    const float* rd0w = (const float*)d_in[4];  const float* rd0b = (const float*)d_in[5];
    const float* rd1w = (const float*)d_in[6];  const float* rd1b = (const float*)d_in[7];
    const float* if0w = (const float*)d_in[8];  const float* if0b = (const float*)d_in[9];
    const float* if1w = (const float*)d_in[10]; const float* if1b = (const float*)d_in[11];
    float* out = (float*)d_out;

    WPtrs wp;
    for (int i = 0; i < 20; i++) wp.p[i] = (const float*)d_in[12 + i];

    const int stage2_smem = (WTOT + 8 * WARPTMP) * 4;   // 63568 B -> 3 CTAs/SM
    cudaFuncSetAttribute(gemm1_kernel, cudaFuncAttributeMaxDynamicSharedMemorySize, SMEM_G1);
    cudaFuncSetAttribute(stage2_kernel, cudaFuncAttributeMaxDynamicSharedMemorySize, stage2_smem);

    prep_w0t<<<dim3(16, 64), dim3(32, 8)>>>(if0w);
    gemm1_kernel<<<dim3(4, 1024), 256, SMEM_G1>>>(bott, if0b, if1w);
    stage2_kernel<<<TOTPTS / 8, 256, stage2_smem>>>(tok, inval, rdiff, wp,
                                                    rd0w, rd0b, rd1w, rd1b, if1b, out);
}

// round 16
// speedup vs baseline: 1.5653x; 1.0079x over previous
#include <cuda_runtime.h>
#include <mma.h>
#include <math.h>
#include <stdint.h>

using namespace nvcuda;

#define TOTPTS 16384
#define MROWS  131072   // TOT*NV
#define KDIM   2048
#define NDIM   512

// Static device scratch (no runtime allocation allowed).
__device__ float g_W0T[(size_t)NDIM * KDIM];       // W0^T [n][k], tf32-RN, 4MB
__device__ float g_part[(size_t)4 * MROWS * 32];   // per-N-chunk partial B32, 64MB

__device__ __forceinline__ float eluf(float x) { return x > 0.f ? x : expm1f(x); }
__device__ __forceinline__ float sigm(float x) { return 1.f / (1.f + expf(-x)); }
__device__ __forceinline__ float wrsum(float v) {
#pragma unroll
    for (int o = 16; o > 0; o >>= 1) v += __shfl_xor_sync(0xffffffffu, v, o);
    return v;
}
__device__ __forceinline__ float rnd_tf32(float x) {
    float r;
    asm("cvt.rna.tf32.f32 %0, %1;" : "=f"(r) : "f"(x));
    return r;
}
__device__ __forceinline__ uint32_t smem_u32(const void* p) {
    uint32_t a;
    asm("{ .reg .u64 t; cvta.to.shared.u64 t, %1; cvt.u32.u64 %0, t; }" : "=r"(a) : "l"(p));
    return a;
}
__device__ __forceinline__ void bulkcp(uint32_t dst, const void* src, uint32_t bytes,
                                       uint32_t bar) {
    asm volatile("cp.async.bulk.shared::cta.global.mbarrier::complete_tx::bytes "
                 "[%0], [%1], %2, [%3];"
                 :: "r"(dst), "l"(src), "r"(bytes), "r"(bar) : "memory");
}
__device__ __forceinline__ void ldsm4(uint32_t& r0, uint32_t& r1, uint32_t& r2, uint32_t& r3,
                                      uint32_t addr) {
    asm volatile("ldmatrix.sync.aligned.m8n8.x4.shared.b16 {%0,%1,%2,%3}, [%4];"
                 : "=r"(r0), "=r"(r1), "=r"(r2), "=r"(r3) : "r"(addr));
}
__device__ __forceinline__ void mma8(float* d, const uint32_t* a, const uint32_t* b) {
    asm volatile("mma.sync.aligned.m16n8k8.row.col.f32.tf32.tf32.f32 "
                 "{%0,%1,%2,%3}, {%4,%5,%6,%7}, {%8,%9}, {%0,%1,%2,%3};"
                 : "+f"(d[0]), "+f"(d[1]), "+f"(d[2]), "+f"(d[3])
                 : "r"(a[0]), "r"(a[1]), "r"(a[2]), "r"(a[3]), "r"(b[0]), "r"(b[1]));
}
#define MBAR_INIT(a, c) asm volatile("mbarrier.init.shared.b64 [%0], %1;" :: "r"(a), "r"(c) : "memory")
#define MBAR_EXPECT(a, tx) asm volatile("mbarrier.arrive.expect_tx.shared.b64 _, [%0], %1;" :: "r"(a), "r"(tx) : "memory")
#define MBAR_WAIT(a, ph) do {                                                              \
    uint32_t _m = (a), _p = (ph), _d;                                                      \
    asm volatile("{\n\t.reg .pred p;\n\t"                                                  \
                 "mbarrier.try_wait.parity.acquire.cta.shared::cta.b64 p, [%1], %2;\n\t"   \
                 "selp.b32 %0, 1, 0, p;\n\t}" : "=r"(_d) : "r"(_m), "r"(_p) : "memory");   \
    if (!_d) {                                                                             \
        asm volatile("{\n\t.reg .pred P1;\n\t"                                             \
            "WL%=:\n\t"                                                                    \
            "mbarrier.try_wait.parity.acquire.cta.shared::cta.b64 P1, [%0], %1, 0x989680;\n\t" \
            "@P1 bra.uni WD%=;\n\t"                                                        \
            "bra.uni WL%=;\n\t"                                                            \
            "WD%=:\n\t}" :: "r"(_m), "r"(_p) : "memory");                                  \
    }                                                                                      \
} while (0)
#define FENCE_PROXY() asm volatile("fence.proxy.async.shared::cta;" ::: "memory")

// ---------------------------------------------------------------------------
// PREP: g_W0T[n][k] = rn_tf32(W0[k][n])
// ---------------------------------------------------------------------------
__global__ void prep_w0t(const float* __restrict__ W0) {
    __shared__ float tile[32][33];
    int n0 = blockIdx.x * 32, k0 = blockIdx.y * 32;
    int tx = threadIdx.x, ty = threadIdx.y;
#pragma unroll
    for (int j = 0; j < 32; j += 8)
        tile[ty + j][tx] = W0[(size_t)(k0 + ty + j) * NDIM + n0 + tx];
    __syncthreads();
#pragma unroll
    for (int j = 0; j < 32; j += 8)
        g_W0T[(size_t)(n0 + ty + j) * KDIM + k0 + tx] = rnd_tf32(tile[tx][ty + j]);
}

// ---------------------------------------------------------------------------
// GEMM1 (at legacy tensor-pipe ceiling — verified rt16 model; unchanged).
// ---------------------------------------------------------------------------
#define STAGEB   36864
#define SMEM_G1  88064
#define HS_F     256
#define W1S_F    17152

__global__ void __launch_bounds__(256, 2) gemm1_kernel(
    const float* __restrict__ X, const float* __restrict__ b0,
    const float* __restrict__ W1)
{
    extern __shared__ float sm[];
    const uint32_t smem = smem_u32(sm);
    const int tid = threadIdx.x, wid = tid >> 5, lane = tid & 31;
    const int p = blockIdx.x, m0 = blockIdx.y * 128, n0 = p * 128;
    const int wm = (wid >> 2) * 64, wn = (wid & 3) * 32;

    if (tid < 128) sm[32 + tid] = b0[n0 + tid];
    if (tid == 0) {
        MBAR_INIT(smem + 16, 1);
        MBAR_INIT(smem + 24, 1);
        FENCE_PROXY();
    }
    __syncthreads();

    const bool isA = tid < 128;
    const int row = tid & 127;
    const float* srcbase = isA ? (X + (size_t)(m0 + row) * KDIM)
                               : (g_W0T + (size_t)(n0 + row) * KDIM);
    const uint32_t dsto = (isA ? 0u : 18432u) + (uint32_t)row * 144u;

    float acc[4][4][4];
#pragma unroll
    for (int g = 0; g < 4; g++)
#pragma unroll
        for (int j = 0; j < 4; j++)
#pragma unroll
            for (int e = 0; e < 4; e++) acc[g][j][e] = 0.f;

    const int rA = lane & 15, hA = (lane >> 4) & 1;
    const int rB = (lane & 7) + ((lane >> 4) & 1) * 8, hB = (lane >> 3) & 1;
    const uint32_t aoff = (uint32_t)(wm + rA) * 144u + (uint32_t)hA * 16u;
    const uint32_t boff = 18432u + (uint32_t)(wn + rB) * 144u + (uint32_t)hB * 16u;

#pragma unroll
    for (int t = 0; t < 2; t++) {
        uint32_t bar = smem + 16 + 8 * t;
        if (tid == 0) MBAR_EXPECT(bar, 32768);
        __syncwarp();
        bulkcp(smem + 1024 + t * STAGEB + dsto, srcbase + t * 32, 128, bar);
    }

    for (int t = 0; t < 64; t++) {
        const int s = t & 1;
        MBAR_WAIT(smem + 16 + 8 * s, (t >> 1) & 1);

        const uint32_t base = smem + 1024 + s * STAGEB;
#pragma unroll
        for (int ks = 0; ks < 4; ks++) {
            uint32_t a[4][4], b[2][4];
#pragma unroll
            for (int g = 0; g < 4; g++)
                ldsm4(a[g][0], a[g][1], a[g][2], a[g][3],
                      base + aoff + (uint32_t)g * 2304u + (uint32_t)ks * 32u);
#pragma unroll
            for (int jj = 0; jj < 2; jj++)
                ldsm4(b[jj][0], b[jj][1], b[jj][2], b[jj][3],
                      base + boff + (uint32_t)jj * 2304u + (uint32_t)ks * 32u);
#pragma unroll
            for (int g = 0; g < 4; g++)
#pragma unroll
                for (int e = 0; e < 4; e++)
                    a[g][e] = __float_as_uint(rnd_tf32(__uint_as_float(a[g][e])));
#pragma unroll
            for (int g = 0; g < 4; g++) {
                mma8(acc[g][0], a[g], &b[0][0]);
                mma8(acc[g][1], a[g], &b[0][2]);
                mma8(acc[g][2], a[g], &b[1][0]);
                mma8(acc[g][3], a[g], &b[1][2]);
            }
        }
        __syncthreads();
        if (t + 2 < 64) {
            uint32_t bar = smem + 16 + 8 * s;
            if (tid == 0) MBAR_EXPECT(bar, 32768);
            bulkcp(smem + 1024 + s * STAGEB + dsto, srcbase + (t + 2) * 32, 128, bar);
        }
    }

    float* Hs  = sm + HS_F;
    float* W1s = sm + W1S_F;
    {
        const int tr = lane >> 2, tc = 2 * (lane & 3);
#pragma unroll
        for (int g = 0; g < 4; g++)
#pragma unroll
            for (int j = 0; j < 4; j++) {
                int R0 = wm + g * 16 + tr, C = wn + j * 8 + tc;
                float b0c0 = sm[32 + C], b0c1 = sm[32 + C + 1];
                float2 v0, v1;
                v0.x = rnd_tf32(eluf(acc[g][j][0] + b0c0));
                v0.y = rnd_tf32(eluf(acc[g][j][1] + b0c1));
                v1.x = rnd_tf32(eluf(acc[g][j][2] + b0c0));
                v1.y = rnd_tf32(eluf(acc[g][j][3] + b0c1));
                *(float2*)&Hs[R0 * 132 + C] = v0;
                *(float2*)&Hs[(R0 + 8) * 132 + C] = v1;
            }
    }
    for (int i = tid; i < 128 * 32; i += 256) {
        int r = i >> 5, c = i & 31;
        W1s[r * 36 + c] = rnd_tf32(W1[(size_t)(n0 + r) * 32 + c]);
    }
    __syncthreads();

    {
        int r0 = wid * 16;
        wmma::fragment<wmma::accumulator, 16, 16, 8, float> oacc[2];
        wmma::fill_fragment(oacc[0], 0.f);
        wmma::fill_fragment(oacc[1], 0.f);
#pragma unroll
        for (int kk = 0; kk < 16; kk++) {
            wmma::fragment<wmma::matrix_a, 16, 16, 8, wmma::precision::tf32, wmma::row_major> af;
            wmma::fragment<wmma::matrix_b, 16, 16, 8, wmma::precision::tf32, wmma::row_major> bf0, bf1;
            wmma::load_matrix_sync(af, &Hs[r0 * 132 + kk * 8], 132);
            wmma::load_matrix_sync(bf0, &W1s[kk * 8 * 36], 36);
            wmma::load_matrix_sync(bf1, &W1s[kk * 8 * 36 + 16], 36);
            wmma::mma_sync(oacc[0], af, bf0, oacc[0]);
            wmma::mma_sync(oacc[1], af, bf1, oacc[1]);
        }
        float* dst = g_part + (size_t)p * MROWS * 32 + (size_t)(m0 + r0) * 32;
        wmma::store_matrix_sync(dst, oacc[0], 32, wmma::mem_row_major);
        wmma::store_matrix_sync(dst + 16, oacc[1], 32, wmma::mem_row_major);
    }
}

// ---------------------------------------------------------------------------
// STAGE2 v4: quad-view weight sharing + 4 CTAs/SM (bf0w, gf0w, bf1w, rd1w
// all in GLOBAL via coalesced __ldg; smem 55.4KB).
// ---------------------------------------------------------------------------
struct WPtrs { const float* p[20]; };

#define WTOT    4180
#define WARPTMP 1208

__global__ void __launch_bounds__(256, 4) stage2_kernel(
    const float* __restrict__ tokG, const void* __restrict__ invG,
    const float* __restrict__ rdiff, WPtrs wp,
    const float* __restrict__ rd0w_, const float* __restrict__ rd0b_,
    const float* __restrict__ rd1w_, const float* __restrict__ rd1b_,
    const float* __restrict__ b1_, float* __restrict__ out)
{
    extern __shared__ float sm[];
    const int tid = threadIdx.x, wid = tid >> 5, lane = tid & 31;

    // weights -> smem (bf0w, bf1w, gf0w excluded; stay global)
    const int srcidx[17] = {0,1,2,3,5,7,8,9,10,11,12,13,14,15,17,18,19};
    const int cnt[17] = {128,8,8,1,64,32,1024,32,1056,33,1024,32,32,1,32,512,16};
    const int off[17] = {0,128,136,144,145,209,241,1265,1297,2353,2386,3410,3442,3474,3475,3507,4019};
    for (int s = 0; s < 17; s++) {
        const float* src = wp.p[srcidx[s]]; float* dst = sm + off[s];
        for (int i = tid; i < cnt[s]; i += 256) dst[i] = src[i];
    }
    for (int i = tid; i < 64; i += 256) sm[4035 + i] = rd0w_[i];
    for (int i = tid; i < 16; i += 256) sm[4099 + i] = rd0b_[i];
    for (int i = tid; i < 32; i += 256) sm[4115 + i] = rd1b_[i];
    for (int i = tid; i < 32; i += 256) sm[4147 + i] = b1_[i];
    __syncthreads();

    const float* nr0w = sm;          const float* nr0b = sm + 128;
    const float* nr1w = sm + 136;    const float* nr1b = sm + 144;
    const float* bf0wg = wp.p[4];    // GLOBAL
    const float* bf0b = sm + 145;
    const float* bf1wg = wp.p[6];    // GLOBAL
    const float* bf1b = sm + 209;
    const float* vf0w = sm + 241;    const float* vf0b = sm + 1265;
    const float* vf1w = sm + 1297;   const float* vf1b = sm + 2353;
    const float* v20w = sm + 2386;   const float* v20b = sm + 3410;
    const float* v21w = sm + 3442;   const float* v21b = sm + 3474;
    const float* gf0wg = wp.p[16];   // GLOBAL
    const float* gf0b = sm + 3475;
    const float* gf1w = sm + 3507;   const float* gf1b = sm + 4019;
    const float* rd0w = sm + 4035;   const float* rd0b = sm + 4099;
    const float* rd1b = sm + 4115;   const float* b1s  = sm + 4147;

    float* T = sm + WTOT + wid * WARPTMP;
    float* tokW = T;          float* bottW = T + 128;  float* xW   = T + 384;
    float* gfW  = T + 640;    float* h256  = T + 768;  float* h33q = T + 1024;
    float* wtW  = T + 1168;   float* w0W   = T + 1176; float* mskW = T + 1184;
    float* visW = T + 1192;   float* w2W   = T + 1200;

    int t = blockIdx.x * 8 + wid;

    const unsigned char* bb = (const unsigned char*)invG;
    int u8f = 0;
    for (int i = lane; i < 256; i += 32) if ((i & 3) && bb[i] == 1) u8f = 1;
    u8f = (__ballot_sync(0xffffffffu, u8f) != 0);

    for (int i = lane; i < 128; i += 32) tokW[i] = tokG[(size_t)t * 128 + i];
    float mv = 0.f;
    if (lane < 8) {
        int idx = t * 8 + lane;
        bool inv = u8f ? (bb[idx] != 0)
                       : (((const unsigned int*)invG)[idx] != 0u);
        mv = inv ? 0.f : 1.f;
    }
    float msum = wrsum(mv);
    if (lane < 8) { mskW[lane] = mv; wtW[lane] = mv / (msum + 1e-8f); }

#pragma unroll
    for (int vp = 0; vp < 4; vp++) {
        size_t rA = (size_t)t * 8 + 2 * vp, rB = rA + 1;
        float rvA = (lane < 4) ? rdiff[rA * 4 + lane] : 0.f;
        float rvB = (lane < 4) ? rdiff[rB * 4 + lane] : 0.f;
        float a0 = __shfl_sync(0xffffffffu, rvA, 0), a1 = __shfl_sync(0xffffffffu, rvA, 1);
        float a2 = __shfl_sync(0xffffffffu, rvA, 2), a3 = __shfl_sync(0xffffffffu, rvA, 3);
        float c0 = __shfl_sync(0xffffffffu, rvB, 0), c1 = __shfl_sync(0xffffffffu, rvB, 1);
        float c2 = __shfl_sync(0xffffffffu, rvB, 2), c3 = __shfl_sync(0xffffffffu, rvB, 3);
        float h0 = 0.f, h1 = 0.f;
        if (lane < 16) {
            h0 = eluf(rd0b[lane] + a0 * rd0w[lane] + a1 * rd0w[16 + lane]
                                 + a2 * rd0w[32 + lane] + a3 * rd0w[48 + lane]);
            h1 = eluf(rd0b[lane] + c0 * rd0w[lane] + c1 * rd0w[16 + lane]
                                 + c2 * rd0w[32 + lane] + c3 * rd0w[48 + lane]);
        }
        float d0 = rd1b[lane], d1 = rd1b[lane];
#pragma unroll
        for (int k = 0; k < 16; k++) {
            float w = __ldg(&rd1w_[k * 32 + lane]);
            d0 += __shfl_sync(0xffffffffu, h0, k) * w;
            d1 += __shfl_sync(0xffffffffu, h1, k) * w;
        }
        float s0 = b1s[lane] + eluf(d0), s1 = b1s[lane] + eluf(d1);
#pragma unroll
        for (int p = 0; p < 4; p++) {
            s0 += g_part[(size_t)p * MROWS * 32 + rA * 32 + lane];
            s1 += g_part[(size_t)p * MROWS * 32 + rB * 32 + lane];
        }
        bottW[2 * vp * 32 + lane] = s0;
        bottW[(2 * vp + 1) * 32 + lane] = s1;
    }
    __syncwarp();

    if (lane < 8) {
        float hh[8];
#pragma unroll
        for (int i = 0; i < 8; i++) hh[i] = nr0b[i];
#pragma unroll
        for (int k = 0; k < 16; k++) {
            float tv = tokW[lane * 16 + k];
#pragma unroll
            for (int i = 0; i < 8; i++) hh[i] += tv * nr0w[k * 8 + i];
        }
        float s = nr1b[0];
#pragma unroll
        for (int i = 0; i < 8; i++) s += eluf(hh[i]) * nr1w[i];
        w0W[lane] = sigm(s) * wtW[lane];
    }
    __syncwarp();

    {
        float m0 = 0.f, m1 = 0.f;
#pragma unroll
        for (int v = 0; v < 8; v++) { float b = bottW[v * 32 + lane]; m0 += b * w0W[v]; m1 += b * wtW[v]; }
        float v0 = 0.f, v1 = 0.f;
#pragma unroll
        for (int v = 0; v < 8; v++) {
            float b = bottW[v * 32 + lane]; float d0 = b - m0, d1 = b - m1;
            v0 += w0W[v] * d0 * d0; v1 += wtW[v] * d1 * d1;
        }
        gfW[lane] = m0; gfW[32 + lane] = v0; gfW[64 + lane] = m1; gfW[96 + lane] = v1;
    }
    __syncwarp();

    float gfc0 = bf0b[lane], gfc1 = bf0b[32 + lane];
#pragma unroll
    for (int k4 = 0; k4 < 32; k4++) {
        float4 g4 = *(float4*)&gfW[k4 * 4];
#pragma unroll
        for (int e = 0; e < 4; e++) {
            int k = k4 * 4 + e;
            float g = (&g4.x)[e];
            gfc0 += g * __ldg(&bf0wg[k * 64 + lane]);
            gfc1 += g * __ldg(&bf0wg[k * 64 + 32 + lane]);
        }
    }

#pragma unroll 1
    for (int sp = 0; sp < 2; sp++) {
        const int vb = sp * 4;
        float a0[4], a1[4];
#pragma unroll
        for (int v = 0; v < 4; v++) { a0[v] = gfc0; a1[v] = gfc1; }
#pragma unroll
        for (int k4 = 0; k4 < 8; k4++) {
            float4 bv[4];
#pragma unroll
            for (int v = 0; v < 4; v++) bv[v] = *(float4*)&bottW[(vb + v) * 32 + k4 * 4];
#pragma unroll
            for (int e = 0; e < 4; e++) {
                int k = k4 * 4 + e;
                float w0 = __ldg(&bf0wg[(128 + k) * 64 + lane]);
                float w1 = __ldg(&bf0wg[(128 + k) * 64 + 32 + lane]);
#pragma unroll
                for (int v = 0; v < 4; v++) {
                    float f = (&bv[v].x)[e];
                    a0[v] += f * w0; a1[v] += f * w1;
                }
            }
        }
#pragma unroll
        for (int k4 = 0; k4 < 4; k4++) {
            float4 tv4[4];
#pragma unroll
            for (int v = 0; v < 4; v++) tv4[v] = *(float4*)&tokW[(vb + v) * 16 + k4 * 4];
#pragma unroll
            for (int e = 0; e < 4; e++) {
                int k = k4 * 4 + e;
                float w0 = __ldg(&bf0wg[(160 + k) * 64 + lane]);
                float w1 = __ldg(&bf0wg[(160 + k) * 64 + 32 + lane]);
#pragma unroll
                for (int v = 0; v < 4; v++) {
                    float f = (&tv4[v].x)[e];
                    a0[v] += f * w0; a1[v] += f * w1;
                }
            }
        }
#pragma unroll
        for (int v = 0; v < 4; v++) {
            h256[v * 64 + lane] = eluf(a0[v]);
            h256[v * 64 + 32 + lane] = eluf(a1[v]);
        }
        __syncwarp();
        {
            float s[4];
#pragma unroll
            for (int v = 0; v < 4; v++) s[v] = bf1b[lane];
#pragma unroll
            for (int k4 = 0; k4 < 16; k4++) {
                float4 hv[4];
#pragma unroll
                for (int v = 0; v < 4; v++) hv[v] = *(float4*)&h256[v * 64 + k4 * 4];
#pragma unroll
                for (int e = 0; e < 4; e++) {
                    float w = __ldg(&bf1wg[(k4 * 4 + e) * 32 + lane]);
#pragma unroll
                    for (int v = 0; v < 4; v++) s[v] += (&hv[v].x)[e] * w;
                }
            }
#pragma unroll
            for (int v = 0; v < 4; v++) xW[(vb + v) * 32 + lane] = eluf(s[v]);
        }
        __syncwarp();
        {
            float dot[4] = {0.f, 0.f, 0.f, 0.f};
#pragma unroll
            for (int k4 = 0; k4 < 8; k4++) {
                float4 xv[4];
#pragma unroll
                for (int v = 0; v < 4; v++) xv[v] = *(float4*)&xW[(vb + v) * 32 + k4 * 4];
#pragma unroll
                for (int e = 0; e < 4; e++) {
                    float w = vf0w[(k4 * 4 + e) * 32 + lane];
#pragma unroll
                    for (int v = 0; v < 4; v++) dot[v] += (&xv[v].x)[e] * w;
                }
            }
#pragma unroll
            for (int v = 0; v < 4; v++)
                h33q[v * 36 + lane] = eluf(vf0b[lane] + wtW[vb + v] * dot[v]);
        }
        __syncwarp();
        float xr[4];
        {
#pragma unroll
            for (int v = 0; v < 4; v++) xr[v] = vf1b[lane];
#pragma unroll
            for (int k4 = 0; k4 < 8; k4++) {
                float4 hq[4];
#pragma unroll
                for (int v = 0; v < 4; v++) hq[v] = *(float4*)&h33q[v * 36 + k4 * 4];
#pragma unroll
                for (int e = 0; e < 4; e++) {
                    float w = vf1w[(k4 * 4 + e) * 33 + lane];
#pragma unroll
                    for (int v = 0; v < 4; v++) xr[v] += (&hq[v].x)[e] * w;
                }
            }
#pragma unroll
            for (int v = 0; v < 4; v++) xr[v] = eluf(xr[v]);
        }
        if (lane < 4) {
            const float* hx = &h33q[lane * 36];
            float a = vf1b[32];
#pragma unroll
            for (int k = 0; k < 32; k++) a += hx[k] * vf1w[k * 33 + 32];
            visW[vb + lane] = sigm(eluf(a)) * mskW[vb + lane];
        }
        __syncwarp();
#pragma unroll
        for (int v = 0; v < 4; v++) xW[(vb + v) * 32 + lane] += xr[v];
        __syncwarp();
        {
            float dot[4] = {0.f, 0.f, 0.f, 0.f};
#pragma unroll
            for (int k4 = 0; k4 < 8; k4++) {
                float4 xv[4];
#pragma unroll
                for (int v = 0; v < 4; v++) xv[v] = *(float4*)&xW[(vb + v) * 32 + k4 * 4];
#pragma unroll
                for (int e = 0; e < 4; e++) {
                    float w = v20w[(k4 * 4 + e) * 32 + lane];
#pragma unroll
                    for (int v = 0; v < 4; v++) dot[v] += (&xv[v].x)[e] * w;
                }
            }
#pragma unroll
            for (int v = 0; v < 4; v++)
                h33q[v * 36 + lane] = eluf(v20b[lane] + visW[vb + v] * dot[v]);
        }
        __syncwarp();
        {
            float wv21 = v21w[lane];
#pragma unroll
            for (int v = 0; v < 4; v++) {
                float s = wrsum(h33q[v * 36 + lane] * wv21) + v21b[0];
                if (lane == 0) w2W[vb + v] = sigm(s) * mskW[vb + v];
            }
        }
        __syncwarp();
    }

    {
        float vv = (lane < 8) ? w2W[lane] : 0.f;
        float s = wrsum(vv);
        if (lane < 8) w2W[lane] = vv / (s + 1e-8f);
    }
    __syncwarp();
    float wbar;
    {
        float vv = (lane < 8) ? w2W[lane] : 0.f;
        wbar = wrsum(vv) * 0.125f;
    }
    {
        float m = 0.f;
#pragma unroll
        for (int v = 0; v < 8; v++) m += xW[v * 32 + lane] * w2W[v];
        float va = 0.f;
#pragma unroll
        for (int v = 0; v < 8; v++) { float dd = xW[v * 32 + lane] - m; va += w2W[v] * dd * dd; }
        gfW[lane] = m; gfW[32 + lane] = va;
        if (lane == 0) gfW[64] = wbar;
    }
    __syncwarp();
    {
        float a = gf0b[lane];
#pragma unroll
        for (int k4 = 0; k4 < 16; k4++) {
            float4 g4 = *(float4*)&gfW[k4 * 4];
#pragma unroll
            for (int e = 0; e < 4; e++)
                a += (&g4.x)[e] * __ldg(&gf0wg[(k4 * 4 + e) * 32 + lane]);
        }
        a += gfW[64] * __ldg(&gf0wg[64 * 32 + lane]);
        h33q[lane] = eluf(a);
    }
    __syncwarp();
    if (lane < 16) {
        float a = gf1b[lane];
#pragma unroll
        for (int k = 0; k < 32; k++) a += h33q[k] * gf1w[k * 16 + lane];
        out[(size_t)t * 16 + lane] = eluf(a);
    }
}

// ---------------------------------------------------------------------------
extern "C" void kernel_launch(void* const* d_in, const int* in_sizes, int n_in,
                              void* d_out, int out_size)
{
    const float* tok   = (const float*)d_in[0];
    const float* bott  = (const float*)d_in[1];
    const float* rdiff = (const float*)d_in[2];
    const void*  inval = (const void*)d_in[3];
    const float* rd0w = (const float*)d_in[4];  const float* rd0b = (const float*)d_in[5];
    const float* rd1w = (const float*)d_in[6];  const float* rd1b = (const float*)d_in[7];
    const float* if0w = (const float*)d_in[8];  const float* if0b = (const float*)d_in[9];
    const float* if1w = (const float*)d_in[10]; const float* if1b = (const float*)d_in[11];
    float* out = (float*)d_out;

    WPtrs wp;
    for (int i = 0; i < 20; i++) wp.p[i] = (const float*)d_in[12 + i];

    const int stage2_smem = (WTOT + 8 * WARPTMP) * 4;   // 55376 B -> 4 CTAs/SM
    cudaFuncSetAttribute(gemm1_kernel, cudaFuncAttributeMaxDynamicSharedMemorySize, SMEM_G1);
    cudaFuncSetAttribute(stage2_kernel, cudaFuncAttributeMaxDynamicSharedMemorySize, stage2_smem);

    prep_w0t<<<dim3(16, 64), dim3(32, 8)>>>(if0w);
    gemm1_kernel<<<dim3(4, 1024), 256, SMEM_G1>>>(bott, if0b, if1w);
    stage2_kernel<<<TOTPTS / 8, 256, stage2_smem>>>(tok, inval, rdiff, wp,
                                                    rd0w, rd0b, rd1w, rd1b, if1b, out);
}